// round 14
// baseline (speedup 1.0000x reference)
#include <cuda_runtime.h>
#include <cuda_bf16.h>
#include <stdint.h>

#define SEQ   2048
#define HID   768
#define NH    12
#define HD    64
#define BATCH 2
#define MROWS 4096   // BATCH*SEQ

// ---------------- device scratch -------------------------------------------
__device__ float g_q[(size_t)MROWS * HID];          // Q fp32
__device__ float g_mrg[(size_t)MROWS * HID];        // merged attn out fp32
__device__ __nv_bfloat16 g_kh[(size_t)MROWS * HID]; // K hi/lo bf16
__device__ __nv_bfloat16 g_kl[(size_t)MROWS * HID];
__device__ __nv_bfloat16 g_vh[(size_t)MROWS * HID]; // V hi/lo bf16
__device__ __nv_bfloat16 g_vl[(size_t)MROWS * HID];
__device__ unsigned char g_mask[MROWS];

// ---------------- warp-MMA / async helpers ---------------------------------
__device__ __forceinline__ uint32_t smem_u32(const void* p) {
    uint32_t a;
    asm("{ .reg .u64 t; cvta.to.shared.u64 t, %1; cvt.u32.u64 %0, t; }"
        : "=r"(a) : "l"(p));
    return a;
}
__device__ __forceinline__ void ldsm_x4(uint32_t& r0, uint32_t& r1,
                                        uint32_t& r2, uint32_t& r3, uint32_t a) {
    asm volatile("ldmatrix.sync.aligned.m8n8.x4.shared.b16 {%0,%1,%2,%3}, [%4];"
                 : "=r"(r0), "=r"(r1), "=r"(r2), "=r"(r3) : "r"(a));
}
__device__ __forceinline__ void ldsm_x4_t(uint32_t& r0, uint32_t& r1,
                                          uint32_t& r2, uint32_t& r3, uint32_t a) {
    asm volatile("ldmatrix.sync.aligned.m8n8.x4.trans.shared.b16 {%0,%1,%2,%3}, [%4];"
                 : "=r"(r0), "=r"(r1), "=r"(r2), "=r"(r3) : "r"(a));
}
__device__ __forceinline__ void mma_bf16(float& d0, float& d1, float& d2, float& d3,
                                         uint32_t a0, uint32_t a1, uint32_t a2,
                                         uint32_t a3, uint32_t b0, uint32_t b1) {
    asm volatile(
        "mma.sync.aligned.m16n8k16.row.col.f32.bf16.bf16.f32 "
        "{%0,%1,%2,%3}, {%4,%5,%6,%7}, {%8,%9}, {%0,%1,%2,%3};"
        : "+f"(d0), "+f"(d1), "+f"(d2), "+f"(d3)
        : "r"(a0), "r"(a1), "r"(a2), "r"(a3), "r"(b0), "r"(b1));
}
__device__ __forceinline__ void cp16(uint32_t s, const void* g) {
    asm volatile("cp.async.cg.shared.global [%0], [%1], 16;"
                 :: "r"(s), "l"(g) : "memory");
}
#define CP_COMMIT() asm volatile("cp.async.commit_group;" ::: "memory")
#define CP_WAIT0()  asm volatile("cp.async.wait_group 0;" ::: "memory")
#define CP_WAIT1()  asm volatile("cp.async.wait_group 1;" ::: "memory")

__device__ __forceinline__ uint32_t packbf(__nv_bfloat16 a, __nv_bfloat16 b) {
    return (uint32_t)__bfloat16_as_ushort(a)
         | ((uint32_t)__bfloat16_as_ushort(b) << 16);
}
__device__ __forceinline__ void split4(float4 v, uint2& hi, uint2& lo) {
    __nv_bfloat16 hx = __float2bfloat16(v.x), hy = __float2bfloat16(v.y);
    __nv_bfloat16 hz = __float2bfloat16(v.z), hw = __float2bfloat16(v.w);
    hi.x = packbf(hx, hy);
    hi.y = packbf(hz, hw);
    lo.x = packbf(__float2bfloat16(v.x - __bfloat162float(hx)),
                  __float2bfloat16(v.y - __bfloat162float(hy)));
    lo.y = packbf(__float2bfloat16(v.z - __bfloat162float(hz)),
                  __float2bfloat16(v.w - __bfloat162float(hw)));
}
__device__ __forceinline__ void splitp(float v, __nv_bfloat16& h, __nv_bfloat16& l) {
    h = __float2bfloat16(v);
    l = __float2bfloat16(v - __bfloat162float(h));
}
// swizzled element offset in a 64-wide bf16 row tile
__device__ __forceinline__ int swz(int row, int col) {
    return row * 64 + (((col >> 3) ^ (row & 7)) << 3) + (col & 7);
}

// ---------------------------------------------------------------------------
// prepass: decode bool mask stored as uint8 or int32
// ---------------------------------------------------------------------------
__global__ void decode_mask(const unsigned char* __restrict__ m, int n)
{
    __shared__ int nonz;
    if (threadIdx.x == 0) nonz = 0;
    __syncthreads();
    for (int i = threadIdx.x; i < n; i += blockDim.x)
        if ((i & 3) && m[i]) atomicOr(&nonz, 1);
    __syncthreads();
    const bool is_u8 = (nonz != 0);
    const int* mi = (const int*)m;
    for (int i = threadIdx.x; i < n; i += blockDim.x)
        g_mask[i] = is_u8 ? (m[i] != 0) : (mi[i] != 0);
}

// ---------------------------------------------------------------------------
// HMMA split-bf16 GEMM, cp.async double-buffered fp32 stages.
// C = A * B^T; per chunk: wait stage -> LDS fp32 -> split -> STS bf16 -> MMA,
// while cp.async streams the next chunk. CTA 128x64, KC=32, 24 chunks.
// smem (dyn): fp32 stages 2x(16K A + 8K B) | bf16 AH/AL/BH/BL = 79872 B.
// ---------------------------------------------------------------------------
#define KC     32
#define LDT    40
#define NCHUNK (HID / KC)      // 24
#define ST_A0  0
#define ST_B0  16384
#define ST_A1  24576
#define ST_B1  40960
#define SM_AH  49152
#define SM_AL  59392
#define SM_BH  69632
#define SM_BL  74752
#define GEMM_SMEM 79872

__global__ __launch_bounds__(256)
void tc_gemm(const float* __restrict__ A_ext, int a_from_mrg,
             const float* __restrict__ B0,
             const float* __restrict__ B1,
             const float* __restrict__ B2,
             float* __restrict__ C_ext, int mode)
{
    extern __shared__ char gsm[];
    const uint32_t uBase = smem_u32(gsm);
    __nv_bfloat16* sAh = (__nv_bfloat16*)(gsm + SM_AH);
    __nv_bfloat16* sAl = (__nv_bfloat16*)(gsm + SM_AL);
    __nv_bfloat16* sBh = (__nv_bfloat16*)(gsm + SM_BH);
    __nv_bfloat16* sBl = (__nv_bfloat16*)(gsm + SM_BL);

    const float* A = a_from_mrg ? (const float*)g_mrg : A_ext;
    const float* B = (blockIdx.z == 0) ? B0 : ((blockIdx.z == 1) ? B1 : B2);

    const int tid = threadIdx.x;
    const int wid = tid >> 5;
    const int lane = tid & 31;
    const int bm = blockIdx.y * 128;
    const int bn = blockIdx.x * 64;
    const int m0 = (wid & 3) * 32;
    const int n0 = (wid >> 2) * 32;

    const int arow = lane & 15, acol = (lane >> 4) * 8;
    const int brow = (lane & 7) + ((lane >> 4) * 8), bcol = ((lane >> 3) & 1) * 8;

    const uint32_t uAh = uBase + SM_AH, uAl = uBase + SM_AL;
    const uint32_t uBh = uBase + SM_BH, uBl = uBase + SM_BL;

    // cp.async seg geometry: seg s -> row s>>3, 16B block (s&7) within 128B row
    const int r4 = tid >> 3;
    const int bo4 = (tid & 7) * 16;

    float acc[2][4][4];
    #pragma unroll
    for (int i = 0; i < 2; i++)
        #pragma unroll
        for (int j = 0; j < 4; j++)
            #pragma unroll
            for (int q = 0; q < 4; q++) acc[i][j][q] = 0.f;

    // prologue: stage 0 <- chunk 0
    {
        const char* Ab = (const char*)(A + (size_t)bm * HID);
        const char* Bb = (const char*)(B + (size_t)bn * HID);
        #pragma unroll
        for (int p = 0; p < 4; p++) {
            const int r = r4 + p * 32;
            cp16(uBase + ST_A0 + r * 128 + bo4, Ab + (size_t)r * (HID * 4) + bo4);
        }
        #pragma unroll
        for (int p = 0; p < 2; p++) {
            const int r = r4 + p * 32;
            cp16(uBase + ST_B0 + r * 128 + bo4, Bb + (size_t)r * (HID * 4) + bo4);
        }
        CP_COMMIT();
    }

    for (int c = 0; c < NCHUNK; c++) {
        const int st = c & 1;
        if (c + 1 < NCHUNK) {
            const uint32_t dA = uBase + (st ? ST_A0 : ST_A1);
            const uint32_t dB = uBase + (st ? ST_B0 : ST_B1);
            const char* Ab = (const char*)(A + (size_t)bm * HID + (c + 1) * KC);
            const char* Bb = (const char*)(B + (size_t)bn * HID + (c + 1) * KC);
            #pragma unroll
            for (int p = 0; p < 4; p++) {
                const int r = r4 + p * 32;
                cp16(dA + r * 128 + bo4, Ab + (size_t)r * (HID * 4) + bo4);
            }
            #pragma unroll
            for (int p = 0; p < 2; p++) {
                const int r = r4 + p * 32;
                cp16(dB + r * 128 + bo4, Bb + (size_t)r * (HID * 4) + bo4);
            }
            CP_COMMIT();
            CP_WAIT1();          // chunk c arrived (c+1 still in flight)
        } else {
            CP_WAIT0();
        }
        __syncthreads();         // stage ready AND prior MMA done with bf16 tiles

        // split fp32 stage -> bf16 hi/lo tiles
        const float* fA = (const float*)(gsm + (st ? ST_A1 : ST_A0));
        const float* fB = (const float*)(gsm + (st ? ST_B1 : ST_B0));
        #pragma unroll
        for (int p = 0; p < 4; p++) {
            const int r = r4 + p * 32;
            const int cc = (tid & 7) * 4;
            float4 v = *(const float4*)(fA + r * 32 + cc);
            uint2 hi, lo;
            split4(v, hi, lo);
            *(uint2*)&sAh[r * LDT + cc] = hi;
            *(uint2*)&sAl[r * LDT + cc] = lo;
        }
        #pragma unroll
        for (int p = 0; p < 2; p++) {
            const int r = r4 + p * 32;
            const int cc = (tid & 7) * 4;
            float4 v = *(const float4*)(fB + r * 32 + cc);
            uint2 hi, lo;
            split4(v, hi, lo);
            *(uint2*)&sBh[r * LDT + cc] = hi;
            *(uint2*)&sBl[r * LDT + cc] = lo;
        }
        __syncthreads();

        #pragma unroll
        for (int ks = 0; ks < KC; ks += 16) {
            #pragma unroll
            for (int g = 0; g < 2; g++) {
                uint32_t b0, b1, b2, b3, c0, c1, c2, c3;
                const uint32_t boff = ((n0 + g * 16 + brow) * LDT + ks + bcol) * 2;
                ldsm_x4(b0, b1, b2, b3, uBh + boff);
                ldsm_x4(c0, c1, c2, c3, uBl + boff);
                #pragma unroll
                for (int mt = 0; mt < 2; mt++) {
                    uint32_t h0, h1, h2, h3, l0, l1, l2, l3;
                    const uint32_t aoff = ((m0 + mt * 16 + arow) * LDT + ks + acol) * 2;
                    ldsm_x4(h0, h1, h2, h3, uAh + aoff);
                    ldsm_x4(l0, l1, l2, l3, uAl + aoff);
                    const int j0 = g * 2, j1 = g * 2 + 1;
                    mma_bf16(acc[mt][j0][0], acc[mt][j0][1], acc[mt][j0][2], acc[mt][j0][3],
                             h0, h1, h2, h3, b0, b1);
                    mma_bf16(acc[mt][j0][0], acc[mt][j0][1], acc[mt][j0][2], acc[mt][j0][3],
                             h0, h1, h2, h3, c0, c1);
                    mma_bf16(acc[mt][j0][0], acc[mt][j0][1], acc[mt][j0][2], acc[mt][j0][3],
                             l0, l1, l2, l3, b0, b1);
                    mma_bf16(acc[mt][j1][0], acc[mt][j1][1], acc[mt][j1][2], acc[mt][j1][3],
                             h0, h1, h2, h3, b2, b3);
                    mma_bf16(acc[mt][j1][0], acc[mt][j1][1], acc[mt][j1][2], acc[mt][j1][3],
                             h0, h1, h2, h3, c2, c3);
                    mma_bf16(acc[mt][j1][0], acc[mt][j1][1], acc[mt][j1][2], acc[mt][j1][3],
                             l0, l1, l2, l3, b2, b3);
                }
            }
        }
    }

    const int erow = lane >> 2, ecol = (lane & 3) * 2;
    if (mode == 1 || blockIdx.z == 0) {
        float* C = (mode == 1) ? C_ext : g_q;
        #pragma unroll
        for (int mt = 0; mt < 2; mt++) {
            #pragma unroll
            for (int nt = 0; nt < 4; nt++) {
                size_t r = (size_t)(bm + m0 + mt * 16 + erow);
                int cc = bn + n0 + nt * 8 + ecol;
                *(float2*)(C + r * HID + cc)       = make_float2(acc[mt][nt][0], acc[mt][nt][1]);
                *(float2*)(C + (r + 8) * HID + cc) = make_float2(acc[mt][nt][2], acc[mt][nt][3]);
            }
        }
    } else {
        __nv_bfloat16* Dh = (blockIdx.z == 1) ? g_kh : g_vh;
        __nv_bfloat16* Dl = (blockIdx.z == 1) ? g_kl : g_vl;
        #pragma unroll
        for (int mt = 0; mt < 2; mt++) {
            #pragma unroll
            for (int nt = 0; nt < 4; nt++) {
                size_t r = (size_t)(bm + m0 + mt * 16 + erow);
                int cc = bn + n0 + nt * 8 + ecol;
                __nv_bfloat16 h0, l0, h1, l1;
                splitp(acc[mt][nt][0], h0, l0);
                splitp(acc[mt][nt][1], h1, l1);
                *(uint32_t*)(Dh + r * HID + cc) = packbf(h0, h1);
                *(uint32_t*)(Dl + r * HID + cc) = packbf(l0, l1);
                splitp(acc[mt][nt][2], h0, l0);
                splitp(acc[mt][nt][3], h1, l1);
                *(uint32_t*)(Dh + (r + 8) * HID + cc) = packbf(h0, h1);
                *(uint32_t*)(Dl + (r + 8) * HID + cc) = packbf(l0, l1);
            }
        }
    }
}

// ---------------------------------------------------------------------------
// HMMA flash attention, cp.async double-buffered K/V (pre-split bf16 hi/lo).
// Full-row mask bias preloaded once; ONE __syncthreads per kv tile.
// smem: Q hi/lo 32KB | 2 stages x 32KB | bias 8KB = 104.25KB -> 2 CTAs/SM.
// ---------------------------------------------------------------------------
#define STAGE_B   32768
#define ATTN_SMEM (32768 + 2 * STAGE_B + SEQ * 4)

__global__ __launch_bounds__(256)
void attn_mma()
{
    extern __shared__ char dynsm[];
    const uint32_t uS  = smem_u32(dynsm);
    const uint32_t uQh = uS, uQl = uS + 16384;
    const uint32_t uKV = uS + 32768;
    float* sBias = (float*)(dynsm + 32768 + 2 * STAGE_B);

    const int tid = threadIdx.x;
    const int w = tid >> 5;
    const int lane = tid & 31;
    const int q0 = blockIdx.x * 128;
    const int b = blockIdx.y / NH;
    const int h = blockIdx.y % NH;

    const size_t base = (size_t)b * SEQ * HID + h * HD;
    const float* Qg = g_q + base;
    const __nv_bfloat16* Khg = g_kh + base;
    const __nv_bfloat16* Klg = g_kl + base;
    const __nv_bfloat16* Vhg = g_vh + base;
    const __nv_bfloat16* Vlg = g_vl + base;
    const unsigned char* mk = g_mask + b * SEQ;

    // per-thread cp.async geometry: 16B seg = (row, 8 bf16 cols)
    const int cr  = tid >> 3;           // 0..31 (+32 with p)
    const int cc8 = (tid & 7) * 8;

    // prologue: stage 0 <- tile 0
    #pragma unroll
    for (int p = 0; p < 2; p++) {
        const int r = cr + p * 32;
        const size_t go = (size_t)r * HID + cc8;
        const uint32_t so = (uint32_t)swz(r, cc8) * 2;
        cp16(uKV + so,          Khg + go);
        cp16(uKV + 8192 + so,   Klg + go);
        cp16(uKV + 16384 + so,  Vhg + go);
        cp16(uKV + 24576 + so,  Vlg + go);
    }
    CP_COMMIT();

    // Q tile (128x64) load + split + swizzle, and full mask-bias preload
    #pragma unroll
    for (int p = 0; p < 8; p++) {
        const int s = p * 256 + tid;
        const int r = s >> 4, c = (s & 15) * 4;
        float4 v = *(const float4*)(Qg + (size_t)(q0 + r) * HID + c);
        uint2 hi, lo;
        split4(v, hi, lo);
        const int off2 = swz(r, c) * 2;
        *(uint2*)(dynsm + off2)         = hi;
        *(uint2*)(dynsm + 16384 + off2) = lo;
    }
    #pragma unroll
    for (int p = 0; p < SEQ / 256; p++) {
        const int i = p * 256 + tid;
        sBias[i] = mk[i] ? 0.f : -1e30f;
    }

    const int m0 = w * 16;
    const int arow = m0 + (lane & 15);
    const int acolb = (lane >> 4) << 3;
    const int browp = (lane & 7) + ((lane >> 4) << 3);
    const int bcolp = ((lane >> 3) & 1) << 3;
    const int vrowp = (lane & 7) + (((lane >> 3) & 1) << 3);
    const int vcolp = ((lane >> 4) & 1) << 3;
    const int ecol2 = (lane & 3) * 2;

    float mr0 = -1e30f, mr1 = -1e30f, lr0 = 0.f, lr1 = 0.f;
    float o[8][4];
    #pragma unroll
    for (int j = 0; j < 8; j++)
        #pragma unroll
        for (int q = 0; q < 4; q++) o[j][q] = 0.f;

    for (int t = 0; t < SEQ / 64; t++) {
        const int buf = t & 1;
        CP_WAIT0();
        __syncthreads();     // stage buf ready; all warps done with buf^1

        if (t + 1 < SEQ / 64) {
            const uint32_t dst = uKV + (buf ^ 1) * STAGE_B;
            #pragma unroll
            for (int p = 0; p < 2; p++) {
                const int r = cr + p * 32;
                const size_t go = (size_t)((t + 1) * 64 + r) * HID + cc8;
                const uint32_t so = (uint32_t)swz(r, cc8) * 2;
                cp16(dst + so,          Khg + go);
                cp16(dst + 8192 + so,   Klg + go);
                cp16(dst + 16384 + so,  Vhg + go);
                cp16(dst + 24576 + so,  Vlg + go);
            }
        }
        CP_COMMIT();

        const uint32_t uKh = uKV + buf * STAGE_B;
        const uint32_t uKl = uKh + 8192;
        const uint32_t uVh = uKh + 16384;
        const uint32_t uVl = uKh + 24576;
        const float* bias = sBias + t * 64;

        // ---- S = Q * K^T (split-bf16, 3 products) ----
        float s_[8][4];
        #pragma unroll
        for (int j = 0; j < 8; j++)
            #pragma unroll
            for (int q = 0; q < 4; q++) s_[j][q] = 0.f;

        #pragma unroll
        for (int ks = 0; ks < 4; ks++) {
            uint32_t h0, h1, h2, h3, l0, l1, l2, l3;
            const uint32_t aoff = (uint32_t)swz(arow, ks * 16 + acolb) * 2;
            ldsm_x4(h0, h1, h2, h3, uQh + aoff);
            ldsm_x4(l0, l1, l2, l3, uQl + aoff);
            #pragma unroll
            for (int g = 0; g < 4; g++) {
                uint32_t kb0, kb1, kb2, kb3, kc0, kc1, kc2, kc3;
                const uint32_t boff =
                    (uint32_t)swz(g * 16 + browp, ks * 16 + bcolp) * 2;
                ldsm_x4(kb0, kb1, kb2, kb3, uKh + boff);
                ldsm_x4(kc0, kc1, kc2, kc3, uKl + boff);
                const int j0 = g * 2, j1 = g * 2 + 1;
                mma_bf16(s_[j0][0], s_[j0][1], s_[j0][2], s_[j0][3], h0, h1, h2, h3, kb0, kb1);
                mma_bf16(s_[j0][0], s_[j0][1], s_[j0][2], s_[j0][3], h0, h1, h2, h3, kc0, kc1);
                mma_bf16(s_[j0][0], s_[j0][1], s_[j0][2], s_[j0][3], l0, l1, l2, l3, kb0, kb1);
                mma_bf16(s_[j1][0], s_[j1][1], s_[j1][2], s_[j1][3], h0, h1, h2, h3, kb2, kb3);
                mma_bf16(s_[j1][0], s_[j1][1], s_[j1][2], s_[j1][3], h0, h1, h2, h3, kc2, kc3);
                mma_bf16(s_[j1][0], s_[j1][1], s_[j1][2], s_[j1][3], l0, l1, l2, l3, kb2, kb3);
            }
        }

        // ---- online softmax (rows fully in-warp) ----
        float mx0 = -1e30f, mx1 = -1e30f;
        #pragma unroll
        for (int j = 0; j < 8; j++) {
            const float b0 = bias[j * 8 + ecol2];
            const float b1 = bias[j * 8 + ecol2 + 1];
            s_[j][0] = fmaf(s_[j][0], 0.125f, b0);
            s_[j][1] = fmaf(s_[j][1], 0.125f, b1);
            s_[j][2] = fmaf(s_[j][2], 0.125f, b0);
            s_[j][3] = fmaf(s_[j][3], 0.125f, b1);
            mx0 = fmaxf(mx0, fmaxf(s_[j][0], s_[j][1]));
            mx1 = fmaxf(mx1, fmaxf(s_[j][2], s_[j][3]));
        }
        #pragma unroll
        for (int d = 1; d < 4; d <<= 1) {
            mx0 = fmaxf(mx0, __shfl_xor_sync(0xffffffffu, mx0, d));
            mx1 = fmaxf(mx1, __shfl_xor_sync(0xffffffffu, mx1, d));
        }
        const float mn0 = fmaxf(mr0, mx0);
        const float mn1 = fmaxf(mr1, mx1);
        const float al0 = __expf(mr0 - mn0);
        const float al1 = __expf(mr1 - mn1);
        mr0 = mn0; mr1 = mn1;

        float rs0 = 0.f, rs1 = 0.f;
        #pragma unroll
        for (int j = 0; j < 8; j++) {
            s_[j][0] = __expf(s_[j][0] - mn0);
            s_[j][1] = __expf(s_[j][1] - mn0);
            s_[j][2] = __expf(s_[j][2] - mn1);
            s_[j][3] = __expf(s_[j][3] - mn1);
            rs0 += s_[j][0] + s_[j][1];
            rs1 += s_[j][2] + s_[j][3];
        }
        #pragma unroll
        for (int d = 1; d < 4; d <<= 1) {
            rs0 += __shfl_xor_sync(0xffffffffu, rs0, d);
            rs1 += __shfl_xor_sync(0xffffffffu, rs1, d);
        }
        lr0 = lr0 * al0 + rs0;
        lr1 = lr1 * al1 + rs1;
        #pragma unroll
        for (int j = 0; j < 8; j++) {
            o[j][0] *= al0; o[j][1] *= al0;
            o[j][2] *= al1; o[j][3] *= al1;
        }

        // ---- O += P * V (split-bf16; P acc-frags -> A-frags directly) ----
        #pragma unroll
        for (int kf = 0; kf < 4; kf++) {
            __nv_bfloat16 ph[8], pl[8];
            splitp(s_[2 * kf][0], ph[0], pl[0]);
            splitp(s_[2 * kf][1], ph[1], pl[1]);
            splitp(s_[2 * kf][2], ph[2], pl[2]);
            splitp(s_[2 * kf][3], ph[3], pl[3]);
            splitp(s_[2 * kf + 1][0], ph[4], pl[4]);
            splitp(s_[2 * kf + 1][1], ph[5], pl[5]);
            splitp(s_[2 * kf + 1][2], ph[6], pl[6]);
            splitp(s_[2 * kf + 1][3], ph[7], pl[7]);
            const uint32_t ah0 = packbf(ph[0], ph[1]), ah1 = packbf(ph[2], ph[3]);
            const uint32_t ah2 = packbf(ph[4], ph[5]), ah3 = packbf(ph[6], ph[7]);
            const uint32_t am0 = packbf(pl[0], pl[1]), am1 = packbf(pl[2], pl[3]);
            const uint32_t am2 = packbf(pl[4], pl[5]), am3 = packbf(pl[6], pl[7]);
            #pragma unroll
            for (int g = 0; g < 4; g++) {
                uint32_t v0, v1, v2, v3, u0, u1, u2, u3;
                const uint32_t voff =
                    (uint32_t)swz(kf * 16 + vrowp, g * 16 + vcolp) * 2;
                ldsm_x4_t(v0, v1, v2, v3, uVh + voff);
                ldsm_x4_t(u0, u1, u2, u3, uVl + voff);
                const int d0 = g * 2, d1 = g * 2 + 1;
                mma_bf16(o[d0][0], o[d0][1], o[d0][2], o[d0][3], ah0, ah1, ah2, ah3, v0, v1);
                mma_bf16(o[d0][0], o[d0][1], o[d0][2], o[d0][3], ah0, ah1, ah2, ah3, u0, u1);
                mma_bf16(o[d0][0], o[d0][1], o[d0][2], o[d0][3], am0, am1, am2, am3, v0, v1);
                mma_bf16(o[d1][0], o[d1][1], o[d1][2], o[d1][3], ah0, ah1, ah2, ah3, v2, v3);
                mma_bf16(o[d1][0], o[d1][1], o[d1][2], o[d1][3], ah0, ah1, ah2, ah3, u2, u3);
                mma_bf16(o[d1][0], o[d1][1], o[d1][2], o[d1][3], am0, am1, am2, am3, v2, v3);
            }
        }
    }

    // ---- epilogue: normalize, write merged [b*SEQ+s][HID] fp32 ----
    const float inv0 = 1.f / lr0;
    const float inv1 = 1.f / lr1;
    const int erow = lane >> 2;
    const size_t r0g = (size_t)(b * SEQ + q0 + m0 + erow) * HID + h * HD;
    const size_t r1g = r0g + 8 * HID;
    #pragma unroll
    for (int dt = 0; dt < 8; dt++) {
        const int cc = dt * 8 + ecol2;
        *(float2*)(g_mrg + r0g + cc) = make_float2(o[dt][0] * inv0, o[dt][1] * inv0);
        *(float2*)(g_mrg + r1g + cc) = make_float2(o[dt][2] * inv1, o[dt][3] * inv1);
    }
}

// ---------------------------------------------------------------------------
extern "C" void kernel_launch(void* const* d_in, const int* in_sizes, int n_in,
                              void* d_out, int out_size)
{
    const float*         x    = (const float*)d_in[0];
    const unsigned char* mask = (const unsigned char*)d_in[1];
    const float*         Wq   = (const float*)d_in[2];
    const float*         Wk   = (const float*)d_in[3];
    const float*         Wv   = (const float*)d_in[4];
    const float*         Wp   = (const float*)d_in[5];
    float*               out  = (float*)d_out;

    cudaFuncSetAttribute(attn_mma, cudaFuncAttributeMaxDynamicSharedMemorySize,
                         ATTN_SMEM);
    cudaFuncSetAttribute(tc_gemm, cudaFuncAttributeMaxDynamicSharedMemorySize,
                         GEMM_SMEM);

    dim3 blk(256);
    decode_mask<<<1, 256>>>(mask, in_sizes[1]);
    // QKV projections (Q -> fp32, K/V -> pre-split bf16 hi/lo)
    tc_gemm<<<dim3(HID / 64, MROWS / 128, 3), blk, GEMM_SMEM>>>(x, 0, Wq, Wk, Wv, nullptr, 0);
    // Attention on tensor cores, cp.async double-buffered K/V
    attn_mma<<<dim3(SEQ / 128, BATCH * NH), blk, ATTN_SMEM>>>();
    // Output projection
    tc_gemm<<<dim3(HID / 64, MROWS / 128, 1), blk, GEMM_SMEM>>>(nullptr, 1, Wp, Wp, Wp, out, 1);
}

// round 15
// speedup vs baseline: 1.1015x; 1.1015x over previous
#include <cuda_runtime.h>
#include <cuda_bf16.h>
#include <stdint.h>

#define SEQ   2048
#define HID   768
#define NH    12
#define HD    64
#define BATCH 2
#define MROWS 4096   // BATCH*SEQ

// ---------------- device scratch -------------------------------------------
__device__ float g_q[(size_t)MROWS * HID];          // Q fp32
__device__ float g_mrg[(size_t)MROWS * HID];        // merged attn out fp32
__device__ __nv_bfloat16 g_kh[(size_t)MROWS * HID]; // K hi/lo bf16
__device__ __nv_bfloat16 g_kl[(size_t)MROWS * HID];
__device__ __nv_bfloat16 g_vh[(size_t)MROWS * HID]; // V hi/lo bf16
__device__ __nv_bfloat16 g_vl[(size_t)MROWS * HID];
__device__ unsigned char g_mask[MROWS];

// ---------------- warp-MMA / async helpers ---------------------------------
__device__ __forceinline__ uint32_t smem_u32(const void* p) {
    uint32_t a;
    asm("{ .reg .u64 t; cvta.to.shared.u64 t, %1; cvt.u32.u64 %0, t; }"
        : "=r"(a) : "l"(p));
    return a;
}
__device__ __forceinline__ void ldsm_x4(uint32_t& r0, uint32_t& r1,
                                        uint32_t& r2, uint32_t& r3, uint32_t a) {
    asm volatile("ldmatrix.sync.aligned.m8n8.x4.shared.b16 {%0,%1,%2,%3}, [%4];"
                 : "=r"(r0), "=r"(r1), "=r"(r2), "=r"(r3) : "r"(a));
}
__device__ __forceinline__ void ldsm_x4_t(uint32_t& r0, uint32_t& r1,
                                          uint32_t& r2, uint32_t& r3, uint32_t a) {
    asm volatile("ldmatrix.sync.aligned.m8n8.x4.trans.shared.b16 {%0,%1,%2,%3}, [%4];"
                 : "=r"(r0), "=r"(r1), "=r"(r2), "=r"(r3) : "r"(a));
}
__device__ __forceinline__ void mma_bf16(float& d0, float& d1, float& d2, float& d3,
                                         uint32_t a0, uint32_t a1, uint32_t a2,
                                         uint32_t a3, uint32_t b0, uint32_t b1) {
    asm volatile(
        "mma.sync.aligned.m16n8k16.row.col.f32.bf16.bf16.f32 "
        "{%0,%1,%2,%3}, {%4,%5,%6,%7}, {%8,%9}, {%0,%1,%2,%3};"
        : "+f"(d0), "+f"(d1), "+f"(d2), "+f"(d3)
        : "r"(a0), "r"(a1), "r"(a2), "r"(a3), "r"(b0), "r"(b1));
}
__device__ __forceinline__ void cp16(uint32_t s, const void* g) {
    asm volatile("cp.async.cg.shared.global [%0], [%1], 16;"
                 :: "r"(s), "l"(g) : "memory");
}
#define CP_COMMIT() asm volatile("cp.async.commit_group;" ::: "memory")
#define CP_WAIT0()  asm volatile("cp.async.wait_group 0;" ::: "memory")

__device__ __forceinline__ uint32_t packbf(__nv_bfloat16 a, __nv_bfloat16 b) {
    return (uint32_t)__bfloat16_as_ushort(a)
         | ((uint32_t)__bfloat16_as_ushort(b) << 16);
}
__device__ __forceinline__ void split4(float4 v, uint2& hi, uint2& lo) {
    __nv_bfloat16 hx = __float2bfloat16(v.x), hy = __float2bfloat16(v.y);
    __nv_bfloat16 hz = __float2bfloat16(v.z), hw = __float2bfloat16(v.w);
    hi.x = packbf(hx, hy);
    hi.y = packbf(hz, hw);
    lo.x = packbf(__float2bfloat16(v.x - __bfloat162float(hx)),
                  __float2bfloat16(v.y - __bfloat162float(hy)));
    lo.y = packbf(__float2bfloat16(v.z - __bfloat162float(hz)),
                  __float2bfloat16(v.w - __bfloat162float(hw)));
}
__device__ __forceinline__ void splitp(float v, __nv_bfloat16& h, __nv_bfloat16& l) {
    h = __float2bfloat16(v);
    l = __float2bfloat16(v - __bfloat162float(h));
}
// swizzled element offset in a 64-wide bf16 row tile
__device__ __forceinline__ int swz(int row, int col) {
    return row * 64 + (((col >> 3) ^ (row & 7)) << 3) + (col & 7);
}

// ---------------------------------------------------------------------------
// prepass: decode bool mask stored as uint8 or int32
// ---------------------------------------------------------------------------
__global__ void decode_mask(const unsigned char* __restrict__ m, int n)
{
    __shared__ int nonz;
    if (threadIdx.x == 0) nonz = 0;
    __syncthreads();
    for (int i = threadIdx.x; i < n; i += blockDim.x)
        if ((i & 3) && m[i]) atomicOr(&nonz, 1);
    __syncthreads();
    const bool is_u8 = (nonz != 0);
    const int* mi = (const int*)m;
    for (int i = threadIdx.x; i < n; i += blockDim.x)
        g_mask[i] = is_u8 ? (m[i] != 0) : (mi[i] != 0);
}

// ---------------------------------------------------------------------------
// HMMA split-bf16 GEMM: C = A * B^T, inline fp32->bf16 split.
// CTA tile 128x128 (halves B traffic + CTA count vs 128x64), 8 warps 4m x 2n,
// warp tile 32x64. KC=64, LDT=72 (R12-proven). Only one B n16-group of frags
// live at a time; A frags loaded once per ks and reused across groups.
// Dynamic smem 73728 B -> 2 CTAs/SM.
// mode 0: z=0 -> g_q fp32; z=1 -> g_kh/g_kl bf16; z=2 -> g_vh/g_vl bf16.
// mode 1: C_ext fp32 (B = B0 = Wp).
// ---------------------------------------------------------------------------
#define KC     64
#define LDT    72
#define NCHUNK (HID / KC)    // 12
#define GA_H   0
#define GA_L   (128 * LDT)
#define GB_H   (2 * 128 * LDT)
#define GB_L   (3 * 128 * LDT)
#define GEMM_SMEM (4 * 128 * LDT * 2)   // 73728 B

__global__ __launch_bounds__(256)
void tc_gemm(const float* __restrict__ A_ext, int a_from_mrg,
             const float* __restrict__ B0,
             const float* __restrict__ B1,
             const float* __restrict__ B2,
             float* __restrict__ C_ext, int mode)
{
    extern __shared__ __nv_bfloat16 gsm[];
    __nv_bfloat16* sAh = gsm + GA_H;
    __nv_bfloat16* sAl = gsm + GA_L;
    __nv_bfloat16* sBh = gsm + GB_H;
    __nv_bfloat16* sBl = gsm + GB_L;

    const float* A = a_from_mrg ? (const float*)g_mrg : A_ext;
    const float* B = (blockIdx.z == 0) ? B0 : ((blockIdx.z == 1) ? B1 : B2);

    const int tid = threadIdx.x;
    const int wid = tid >> 5;
    const int lane = tid & 31;
    const int bm = blockIdx.y * 128;
    const int bn = blockIdx.x * 128;
    const int m0 = (wid & 3) * 32;      // warp m origin (2 x m16)
    const int n0 = (wid >> 2) * 64;     // warp n origin (4 x n16)

    const int arow = lane & 15, acol = (lane >> 4) * 8;
    const int brow = (lane & 7) + ((lane >> 4) * 8), bcol = ((lane >> 3) & 1) * 8;

    const uint32_t uAh = smem_u32(sAh), uAl = smem_u32(sAl);
    const uint32_t uBh = smem_u32(sBh), uBl = smem_u32(sBl);

    float acc[2][8][4];
    #pragma unroll
    for (int i = 0; i < 2; i++)
        #pragma unroll
        for (int j = 0; j < 8; j++)
            #pragma unroll
            for (int q = 0; q < 4; q++) acc[i][j][q] = 0.f;

    for (int c = 0; c < NCHUNK; c++) {
        const int k0g = c * KC;
        __syncthreads();
        // A and B tiles each 128x64 fp32: 2048 float4 segs -> 8/thread each
        #pragma unroll
        for (int p = 0; p < 8; p++) {
            const int s = tid + p * 256;
            const int r = s >> 4, cc = (s & 15) * 4;
            float4 v = *(const float4*)(A + (size_t)(bm + r) * HID + k0g + cc);
            uint2 hi, lo;
            split4(v, hi, lo);
            *(uint2*)&sAh[r * LDT + cc] = hi;
            *(uint2*)&sAl[r * LDT + cc] = lo;
        }
        #pragma unroll
        for (int p = 0; p < 8; p++) {
            const int s = tid + p * 256;
            const int r = s >> 4, cc = (s & 15) * 4;
            float4 v = *(const float4*)(B + (size_t)(bn + r) * HID + k0g + cc);
            uint2 hi, lo;
            split4(v, hi, lo);
            *(uint2*)&sBh[r * LDT + cc] = hi;
            *(uint2*)&sBl[r * LDT + cc] = lo;
        }
        __syncthreads();

        #pragma unroll
        for (int ks = 0; ks < KC; ks += 16) {
            // A fragments for both m16 tiles (hi+lo), loaded once per ks
            uint32_t ah0[4], ah1[4], al0[4], al1[4];
            {
                const uint32_t a0 = ((m0 + arow) * LDT + ks + acol) * 2;
                const uint32_t a1 = ((m0 + 16 + arow) * LDT + ks + acol) * 2;
                ldsm_x4(ah0[0], ah0[1], ah0[2], ah0[3], uAh + a0);
                ldsm_x4(ah1[0], ah1[1], ah1[2], ah1[3], uAh + a1);
                ldsm_x4(al0[0], al0[1], al0[2], al0[3], uAl + a0);
                ldsm_x4(al1[0], al1[1], al1[2], al1[3], uAl + a1);
            }
            #pragma unroll
            for (int g = 0; g < 4; g++) {        // four n16 groups
                uint32_t b0, b1, b2, b3, c0, c1, c2, c3;
                const uint32_t boff = ((n0 + g * 16 + brow) * LDT + ks + bcol) * 2;
                ldsm_x4(b0, b1, b2, b3, uBh + boff);
                ldsm_x4(c0, c1, c2, c3, uBl + boff);
                const int j0 = g * 2, j1 = g * 2 + 1;
                mma_bf16(acc[0][j0][0], acc[0][j0][1], acc[0][j0][2], acc[0][j0][3],
                         ah0[0], ah0[1], ah0[2], ah0[3], b0, b1);
                mma_bf16(acc[0][j0][0], acc[0][j0][1], acc[0][j0][2], acc[0][j0][3],
                         ah0[0], ah0[1], ah0[2], ah0[3], c0, c1);
                mma_bf16(acc[0][j0][0], acc[0][j0][1], acc[0][j0][2], acc[0][j0][3],
                         al0[0], al0[1], al0[2], al0[3], b0, b1);
                mma_bf16(acc[0][j1][0], acc[0][j1][1], acc[0][j1][2], acc[0][j1][3],
                         ah0[0], ah0[1], ah0[2], ah0[3], b2, b3);
                mma_bf16(acc[0][j1][0], acc[0][j1][1], acc[0][j1][2], acc[0][j1][3],
                         ah0[0], ah0[1], ah0[2], ah0[3], c2, c3);
                mma_bf16(acc[0][j1][0], acc[0][j1][1], acc[0][j1][2], acc[0][j1][3],
                         al0[0], al0[1], al0[2], al0[3], b2, b3);
                mma_bf16(acc[1][j0][0], acc[1][j0][1], acc[1][j0][2], acc[1][j0][3],
                         ah1[0], ah1[1], ah1[2], ah1[3], b0, b1);
                mma_bf16(acc[1][j0][0], acc[1][j0][1], acc[1][j0][2], acc[1][j0][3],
                         ah1[0], ah1[1], ah1[2], ah1[3], c0, c1);
                mma_bf16(acc[1][j0][0], acc[1][j0][1], acc[1][j0][2], acc[1][j0][3],
                         al1[0], al1[1], al1[2], al1[3], b0, b1);
                mma_bf16(acc[1][j1][0], acc[1][j1][1], acc[1][j1][2], acc[1][j1][3],
                         ah1[0], ah1[1], ah1[2], ah1[3], b2, b3);
                mma_bf16(acc[1][j1][0], acc[1][j1][1], acc[1][j1][2], acc[1][j1][3],
                         ah1[0], ah1[1], ah1[2], ah1[3], c2, c3);
                mma_bf16(acc[1][j1][0], acc[1][j1][1], acc[1][j1][2], acc[1][j1][3],
                         al1[0], al1[1], al1[2], al1[3], b2, b3);
            }
        }
    }

    const int erow = lane >> 2, ecol = (lane & 3) * 2;
    if (mode == 1 || blockIdx.z == 0) {
        float* C = (mode == 1) ? C_ext : g_q;
        #pragma unroll
        for (int mt = 0; mt < 2; mt++) {
            #pragma unroll
            for (int nt = 0; nt < 8; nt++) {
                size_t r = (size_t)(bm + m0 + mt * 16 + erow);
                int cc = bn + n0 + nt * 8 + ecol;
                *(float2*)(C + r * HID + cc)       = make_float2(acc[mt][nt][0], acc[mt][nt][1]);
                *(float2*)(C + (r + 8) * HID + cc) = make_float2(acc[mt][nt][2], acc[mt][nt][3]);
            }
        }
    } else {
        __nv_bfloat16* Dh = (blockIdx.z == 1) ? g_kh : g_vh;
        __nv_bfloat16* Dl = (blockIdx.z == 1) ? g_kl : g_vl;
        #pragma unroll
        for (int mt = 0; mt < 2; mt++) {
            #pragma unroll
            for (int nt = 0; nt < 8; nt++) {
                size_t r = (size_t)(bm + m0 + mt * 16 + erow);
                int cc = bn + n0 + nt * 8 + ecol;
                __nv_bfloat16 h0, l0, h1, l1;
                splitp(acc[mt][nt][0], h0, l0);
                splitp(acc[mt][nt][1], h1, l1);
                *(uint32_t*)(Dh + r * HID + cc) = packbf(h0, h1);
                *(uint32_t*)(Dl + r * HID + cc) = packbf(l0, l1);
                splitp(acc[mt][nt][2], h0, l0);
                splitp(acc[mt][nt][3], h1, l1);
                *(uint32_t*)(Dh + (r + 8) * HID + cc) = packbf(h0, h1);
                *(uint32_t*)(Dl + (r + 8) * HID + cc) = packbf(l0, l1);
            }
        }
    }
}

// ---------------------------------------------------------------------------
// HMMA flash attention, cp.async double-buffered K/V (pre-split bf16 hi/lo).
// Full-row mask bias preloaded once; ONE __syncthreads per kv tile.
// smem: Q hi/lo 32KB | 2 stages x 32KB | bias 8KB = 104.25KB -> 2 CTAs/SM.
// (unchanged from the 495.6us R12 pass)
// ---------------------------------------------------------------------------
#define STAGE_B   32768
#define ATTN_SMEM (32768 + 2 * STAGE_B + SEQ * 4)

__global__ __launch_bounds__(256)
void attn_mma()
{
    extern __shared__ char dynsm[];
    const uint32_t uS  = smem_u32(dynsm);
    const uint32_t uQh = uS, uQl = uS + 16384;
    const uint32_t uKV = uS + 32768;
    float* sBias = (float*)(dynsm + 32768 + 2 * STAGE_B);

    const int tid = threadIdx.x;
    const int w = tid >> 5;
    const int lane = tid & 31;
    const int q0 = blockIdx.x * 128;
    const int b = blockIdx.y / NH;
    const int h = blockIdx.y % NH;

    const size_t base = (size_t)b * SEQ * HID + h * HD;
    const float* Qg = g_q + base;
    const __nv_bfloat16* Khg = g_kh + base;
    const __nv_bfloat16* Klg = g_kl + base;
    const __nv_bfloat16* Vhg = g_vh + base;
    const __nv_bfloat16* Vlg = g_vl + base;
    const unsigned char* mk = g_mask + b * SEQ;

    const int cr  = tid >> 3;
    const int cc8 = (tid & 7) * 8;

    #pragma unroll
    for (int p = 0; p < 2; p++) {
        const int r = cr + p * 32;
        const size_t go = (size_t)r * HID + cc8;
        const uint32_t so = (uint32_t)swz(r, cc8) * 2;
        cp16(uKV + so,          Khg + go);
        cp16(uKV + 8192 + so,   Klg + go);
        cp16(uKV + 16384 + so,  Vhg + go);
        cp16(uKV + 24576 + so,  Vlg + go);
    }
    CP_COMMIT();

    #pragma unroll
    for (int p = 0; p < 8; p++) {
        const int s = p * 256 + tid;
        const int r = s >> 4, c = (s & 15) * 4;
        float4 v = *(const float4*)(Qg + (size_t)(q0 + r) * HID + c);
        uint2 hi, lo;
        split4(v, hi, lo);
        const int off2 = swz(r, c) * 2;
        *(uint2*)(dynsm + off2)         = hi;
        *(uint2*)(dynsm + 16384 + off2) = lo;
    }
    #pragma unroll
    for (int p = 0; p < SEQ / 256; p++) {
        const int i = p * 256 + tid;
        sBias[i] = mk[i] ? 0.f : -1e30f;
    }

    const int m0 = w * 16;
    const int arow = m0 + (lane & 15);
    const int acolb = (lane >> 4) << 3;
    const int browp = (lane & 7) + ((lane >> 4) << 3);
    const int bcolp = ((lane >> 3) & 1) << 3;
    const int vrowp = (lane & 7) + (((lane >> 3) & 1) << 3);
    const int vcolp = ((lane >> 4) & 1) << 3;
    const int ecol2 = (lane & 3) * 2;

    float mr0 = -1e30f, mr1 = -1e30f, lr0 = 0.f, lr1 = 0.f;
    float o[8][4];
    #pragma unroll
    for (int j = 0; j < 8; j++)
        #pragma unroll
        for (int q = 0; q < 4; q++) o[j][q] = 0.f;

    for (int t = 0; t < SEQ / 64; t++) {
        const int buf = t & 1;
        CP_WAIT0();
        __syncthreads();

        if (t + 1 < SEQ / 64) {
            const uint32_t dst = uKV + (buf ^ 1) * STAGE_B;
            #pragma unroll
            for (int p = 0; p < 2; p++) {
                const int r = cr + p * 32;
                const size_t go = (size_t)((t + 1) * 64 + r) * HID + cc8;
                const uint32_t so = (uint32_t)swz(r, cc8) * 2;
                cp16(dst + so,          Khg + go);
                cp16(dst + 8192 + so,   Klg + go);
                cp16(dst + 16384 + so,  Vhg + go);
                cp16(dst + 24576 + so,  Vlg + go);
            }
        }
        CP_COMMIT();

        const uint32_t uKh = uKV + buf * STAGE_B;
        const uint32_t uKl = uKh + 8192;
        const uint32_t uVh = uKh + 16384;
        const uint32_t uVl = uKh + 24576;
        const float* bias = sBias + t * 64;

        float s_[8][4];
        #pragma unroll
        for (int j = 0; j < 8; j++)
            #pragma unroll
            for (int q = 0; q < 4; q++) s_[j][q] = 0.f;

        #pragma unroll
        for (int ks = 0; ks < 4; ks++) {
            uint32_t h0, h1, h2, h3, l0, l1, l2, l3;
            const uint32_t aoff = (uint32_t)swz(arow, ks * 16 + acolb) * 2;
            ldsm_x4(h0, h1, h2, h3, uQh + aoff);
            ldsm_x4(l0, l1, l2, l3, uQl + aoff);
            #pragma unroll
            for (int g = 0; g < 4; g++) {
                uint32_t kb0, kb1, kb2, kb3, kc0, kc1, kc2, kc3;
                const uint32_t boff =
                    (uint32_t)swz(g * 16 + browp, ks * 16 + bcolp) * 2;
                ldsm_x4(kb0, kb1, kb2, kb3, uKh + boff);
                ldsm_x4(kc0, kc1, kc2, kc3, uKl + boff);
                const int j0 = g * 2, j1 = g * 2 + 1;
                mma_bf16(s_[j0][0], s_[j0][1], s_[j0][2], s_[j0][3], h0, h1, h2, h3, kb0, kb1);
                mma_bf16(s_[j0][0], s_[j0][1], s_[j0][2], s_[j0][3], h0, h1, h2, h3, kc0, kc1);
                mma_bf16(s_[j0][0], s_[j0][1], s_[j0][2], s_[j0][3], l0, l1, l2, l3, kb0, kb1);
                mma_bf16(s_[j1][0], s_[j1][1], s_[j1][2], s_[j1][3], h0, h1, h2, h3, kb2, kb3);
                mma_bf16(s_[j1][0], s_[j1][1], s_[j1][2], s_[j1][3], h0, h1, h2, h3, kc2, kc3);
                mma_bf16(s_[j1][0], s_[j1][1], s_[j1][2], s_[j1][3], l0, l1, l2, l3, kb2, kb3);
            }
        }

        float mx0 = -1e30f, mx1 = -1e30f;
        #pragma unroll
        for (int j = 0; j < 8; j++) {
            const float b0 = bias[j * 8 + ecol2];
            const float b1 = bias[j * 8 + ecol2 + 1];
            s_[j][0] = fmaf(s_[j][0], 0.125f, b0);
            s_[j][1] = fmaf(s_[j][1], 0.125f, b1);
            s_[j][2] = fmaf(s_[j][2], 0.125f, b0);
            s_[j][3] = fmaf(s_[j][3], 0.125f, b1);
            mx0 = fmaxf(mx0, fmaxf(s_[j][0], s_[j][1]));
            mx1 = fmaxf(mx1, fmaxf(s_[j][2], s_[j][3]));
        }
        #pragma unroll
        for (int d = 1; d < 4; d <<= 1) {
            mx0 = fmaxf(mx0, __shfl_xor_sync(0xffffffffu, mx0, d));
            mx1 = fmaxf(mx1, __shfl_xor_sync(0xffffffffu, mx1, d));
        }
        const float mn0 = fmaxf(mr0, mx0);
        const float mn1 = fmaxf(mr1, mx1);
        const float al0 = __expf(mr0 - mn0);
        const float al1 = __expf(mr1 - mn1);
        mr0 = mn0; mr1 = mn1;

        float rs0 = 0.f, rs1 = 0.f;
        #pragma unroll
        for (int j = 0; j < 8; j++) {
            s_[j][0] = __expf(s_[j][0] - mn0);
            s_[j][1] = __expf(s_[j][1] - mn0);
            s_[j][2] = __expf(s_[j][2] - mn1);
            s_[j][3] = __expf(s_[j][3] - mn1);
            rs0 += s_[j][0] + s_[j][1];
            rs1 += s_[j][2] + s_[j][3];
        }
        #pragma unroll
        for (int d = 1; d < 4; d <<= 1) {
            rs0 += __shfl_xor_sync(0xffffffffu, rs0, d);
            rs1 += __shfl_xor_sync(0xffffffffu, rs1, d);
        }
        lr0 = lr0 * al0 + rs0;
        lr1 = lr1 * al1 + rs1;
        #pragma unroll
        for (int j = 0; j < 8; j++) {
            o[j][0] *= al0; o[j][1] *= al0;
            o[j][2] *= al1; o[j][3] *= al1;
        }

        #pragma unroll
        for (int kf = 0; kf < 4; kf++) {
            __nv_bfloat16 ph[8], pl[8];
            splitp(s_[2 * kf][0], ph[0], pl[0]);
            splitp(s_[2 * kf][1], ph[1], pl[1]);
            splitp(s_[2 * kf][2], ph[2], pl[2]);
            splitp(s_[2 * kf][3], ph[3], pl[3]);
            splitp(s_[2 * kf + 1][0], ph[4], pl[4]);
            splitp(s_[2 * kf + 1][1], ph[5], pl[5]);
            splitp(s_[2 * kf + 1][2], ph[6], pl[6]);
            splitp(s_[2 * kf + 1][3], ph[7], pl[7]);
            const uint32_t ah0 = packbf(ph[0], ph[1]), ah1 = packbf(ph[2], ph[3]);
            const uint32_t ah2 = packbf(ph[4], ph[5]), ah3 = packbf(ph[6], ph[7]);
            const uint32_t am0 = packbf(pl[0], pl[1]), am1 = packbf(pl[2], pl[3]);
            const uint32_t am2 = packbf(pl[4], pl[5]), am3 = packbf(pl[6], pl[7]);
            #pragma unroll
            for (int g = 0; g < 4; g++) {
                uint32_t v0, v1, v2, v3, u0, u1, u2, u3;
                const uint32_t voff =
                    (uint32_t)swz(kf * 16 + vrowp, g * 16 + vcolp) * 2;
                ldsm_x4_t(v0, v1, v2, v3, uVh + voff);
                ldsm_x4_t(u0, u1, u2, u3, uVl + voff);
                const int d0 = g * 2, d1 = g * 2 + 1;
                mma_bf16(o[d0][0], o[d0][1], o[d0][2], o[d0][3], ah0, ah1, ah2, ah3, v0, v1);
                mma_bf16(o[d0][0], o[d0][1], o[d0][2], o[d0][3], ah0, ah1, ah2, ah3, u0, u1);
                mma_bf16(o[d0][0], o[d0][1], o[d0][2], o[d0][3], am0, am1, am2, am3, v0, v1);
                mma_bf16(o[d1][0], o[d1][1], o[d1][2], o[d1][3], ah0, ah1, ah2, ah3, v2, v3);
                mma_bf16(o[d1][0], o[d1][1], o[d1][2], o[d1][3], ah0, ah1, ah2, ah3, u2, u3);
                mma_bf16(o[d1][0], o[d1][1], o[d1][2], o[d1][3], am0, am1, am2, am3, v2, v3);
            }
        }
    }

    const float inv0 = 1.f / lr0;
    const float inv1 = 1.f / lr1;
    const int erow = lane >> 2;
    const size_t r0g = (size_t)(b * SEQ + q0 + m0 + erow) * HID + h * HD;
    const size_t r1g = r0g + 8 * HID;
    #pragma unroll
    for (int dt = 0; dt < 8; dt++) {
        const int cc = dt * 8 + ecol2;
        *(float2*)(g_mrg + r0g + cc) = make_float2(o[dt][0] * inv0, o[dt][1] * inv0);
        *(float2*)(g_mrg + r1g + cc) = make_float2(o[dt][2] * inv1, o[dt][3] * inv1);
    }
}

// ---------------------------------------------------------------------------
extern "C" void kernel_launch(void* const* d_in, const int* in_sizes, int n_in,
                              void* d_out, int out_size)
{
    const float*         x    = (const float*)d_in[0];
    const unsigned char* mask = (const unsigned char*)d_in[1];
    const float*         Wq   = (const float*)d_in[2];
    const float*         Wk   = (const float*)d_in[3];
    const float*         Wv   = (const float*)d_in[4];
    const float*         Wp   = (const float*)d_in[5];
    float*               out  = (float*)d_out;

    cudaFuncSetAttribute(attn_mma, cudaFuncAttributeMaxDynamicSharedMemorySize,
                         ATTN_SMEM);
    cudaFuncSetAttribute(tc_gemm, cudaFuncAttributeMaxDynamicSharedMemorySize,
                         GEMM_SMEM);

    dim3 blk(256);
    decode_mask<<<1, 256>>>(mask, in_sizes[1]);
    // QKV projections (Q -> fp32, K/V -> pre-split bf16 hi/lo)
    tc_gemm<<<dim3(HID / 128, MROWS / 128, 3), blk, GEMM_SMEM>>>(x, 0, Wq, Wk, Wv, nullptr, 0);
    // Attention on tensor cores, cp.async double-buffered K/V
    attn_mma<<<dim3(SEQ / 128, BATCH * NH), blk, ATTN_SMEM>>>();
    // Output projection
    tc_gemm<<<dim3(HID / 128, MROWS / 128, 1), blk, GEMM_SMEM>>>(nullptr, 1, Wp, Wp, Wp, out, 1);
}